// round 2
// baseline (speedup 1.0000x reference)
#include <cuda_runtime.h>
#include <cstdint>
#include <cstdio>

#define NN 100000
#define FF 256

// ---------------- scratch (device globals; no allocation allowed) ----------------
__device__ float g_xw0[(size_t)NN * FF];   // X @ W_A
__device__ float g_xw1[(size_t)NN * FF];   // X @ W_A2
__device__ float g_mlp[(size_t)NN * FF];   // relu(X @ W_mlp)
__device__ float g_acc0[(size_t)NN * FF];  // spmm accumulator A
__device__ float g_acc1[(size_t)NN * FF];  // spmm accumulator A2
__device__ float g_colsum[3 * FF];
__device__ float g_v[3 * FF];              // v0,v1,v2 gate vectors

// ---------------- zero scratch ----------------
__global__ void zero_kernel(int n) {
    size_t nf4 = (size_t)n * (FF / 4);
    size_t stride = (size_t)gridDim.x * blockDim.x;
    float4 z = make_float4(0.f, 0.f, 0.f, 0.f);
    float4* a0 = reinterpret_cast<float4*>(g_acc0);
    float4* a1 = reinterpret_cast<float4*>(g_acc1);
    for (size_t i = (size_t)blockIdx.x * blockDim.x + threadIdx.x; i < nf4; i += stride) {
        a0[i] = z;
        a1[i] = z;
    }
    size_t t = (size_t)blockIdx.x * blockDim.x + threadIdx.x;
    if (t < 3 * FF) g_colsum[t] = 0.f;
}

// ---------------- GEMM: out[z] = X @ W[z], relu for z==2 ----------------
// BM=128, BN=64, BK=16, 256 threads, TM=8, TN=4
__global__ __launch_bounds__(256) void gemm_kernel(
    const float* __restrict__ X,
    const float* __restrict__ W0, const float* __restrict__ W1, const float* __restrict__ W2,
    int n)
{
    constexpr int BM = 128, BN = 64, BK = 16, TM = 8, TN = 4;
    __shared__ float Xs[BK][BM];
    __shared__ float Ws[BK][BN];

    const int z = blockIdx.z;
    const float* W = (z == 0) ? W0 : ((z == 1) ? W1 : W2);
    float* out = (z == 0) ? g_xw0 : ((z == 1) ? g_xw1 : g_mlp);

    const int row0 = blockIdx.y * BM;
    const int col0 = blockIdx.x * BN;
    const int tid = threadIdx.x;
    const int tx = tid & 15;   // 0..15  -> TN*tx cols
    const int ty = tid >> 4;   // 0..15  -> TM*ty rows

    float acc[TM][TN];
#pragma unroll
    for (int i = 0; i < TM; i++)
#pragma unroll
        for (int j = 0; j < TN; j++) acc[i][j] = 0.f;

    for (int k0 = 0; k0 < FF; k0 += BK) {
        // load X tile: 128x16 = 512 float4, 2 per thread (transposed into Xs[k][m])
#pragma unroll
        for (int it = 0; it < 2; it++) {
            int idx = tid + it * 256;      // 0..511
            int r = idx >> 2;              // 0..127
            int kq = (idx & 3) * 4;        // 0,4,8,12
            float4 v = make_float4(0.f, 0.f, 0.f, 0.f);
            int gr = row0 + r;
            if (gr < n)
                v = *reinterpret_cast<const float4*>(X + (size_t)gr * FF + k0 + kq);
            Xs[kq + 0][r] = v.x;
            Xs[kq + 1][r] = v.y;
            Xs[kq + 2][r] = v.z;
            Xs[kq + 3][r] = v.w;
        }
        // load W tile: 16x64 = 256 float4, 1 per thread
        {
            int r = tid >> 4;            // 0..15
            int cq = (tid & 15) * 4;     // 0..60
            float4 v = *reinterpret_cast<const float4*>(W + (size_t)(k0 + r) * FF + col0 + cq);
            *reinterpret_cast<float4*>(&Ws[r][cq]) = v;
        }
        __syncthreads();

#pragma unroll
        for (int kk = 0; kk < BK; kk++) {
            float4 a0 = *reinterpret_cast<const float4*>(&Xs[kk][ty * TM]);
            float4 a1 = *reinterpret_cast<const float4*>(&Xs[kk][ty * TM + 4]);
            float4 b = *reinterpret_cast<const float4*>(&Ws[kk][tx * TN]);
            float a[TM] = {a0.x, a0.y, a0.z, a0.w, a1.x, a1.y, a1.z, a1.w};
            float bb[TN] = {b.x, b.y, b.z, b.w};
#pragma unroll
            for (int i = 0; i < TM; i++)
#pragma unroll
                for (int j = 0; j < TN; j++) acc[i][j] += a[i] * bb[j];
        }
        __syncthreads();
    }

#pragma unroll
    for (int i = 0; i < TM; i++) {
        int gr = row0 + ty * TM + i;
        if (gr < n) {
            float4 v = make_float4(acc[i][0], acc[i][1], acc[i][2], acc[i][3]);
            if (z == 2) {
                v.x = fmaxf(v.x, 0.f); v.y = fmaxf(v.y, 0.f);
                v.z = fmaxf(v.z, 0.f); v.w = fmaxf(v.w, 0.f);
            }
            *reinterpret_cast<float4*>(out + (size_t)gr * FF + col0 + tx * TN) = v;
        }
    }
}

// ---------------- SpMM: acc[row[e]] += val[e] * x[col[e]]  (one warp per edge) ----------------
// NOTE: source/dest buffers are selected INSIDE the kernel (device globals must
// never be passed as host-side kernel arguments — host sees the host shadow
// address, which GB300 ATS happily dereferences into host memory).
__device__ __forceinline__ void red_add_v4(float* p, float4 v) {
    asm volatile("red.relaxed.gpu.global.add.v4.f32 [%0], {%1,%2,%3,%4};"
                 :: "l"(p), "f"(v.x), "f"(v.y), "f"(v.z), "f"(v.w)
                 : "memory");
}

__global__ __launch_bounds__(256) void spmm_kernel(
    const int* __restrict__ rowA, const int* __restrict__ colA, const float* __restrict__ valA,
    const int* __restrict__ rowB, const int* __restrict__ colB, const float* __restrict__ valB,
    int E)
{
    const int m = blockIdx.y;
    const int* __restrict__ row = (m == 0) ? rowA : rowB;
    const int* __restrict__ col = (m == 0) ? colA : colB;
    const float* __restrict__ val = (m == 0) ? valA : valB;
    const float* __restrict__ x = (m == 0) ? g_xw0 : g_xw1;
    float* __restrict__ acc = (m == 0) ? g_acc0 : g_acc1;

    int warp = (int)(((size_t)blockIdx.x * blockDim.x + threadIdx.x) >> 5);
    int lane = threadIdx.x & 31;
    if (warp >= E) return;
    int r = __ldg(row + warp);
    int c = __ldg(col + warp);
    float v = __ldg(val + warp);
    const float4* xs = reinterpret_cast<const float4*>(x + (size_t)c * FF);
    float4 a = __ldg(xs + lane);
    float4 b = __ldg(xs + lane + 32);
    a.x *= v; a.y *= v; a.z *= v; a.w *= v;
    b.x *= v; b.y *= v; b.z *= v; b.w *= v;
    float* dst = acc + (size_t)r * FF;
    red_add_v4(dst + lane * 4, a);
    red_add_v4(dst + 128 + lane * 4, b);
}

// ---------------- column sums of relu(acc0), relu(acc1), mlp ----------------
__global__ __launch_bounds__(256) void colsum_kernel(int n) {
    int c = threadIdx.x;
    float s0 = 0.f, s1 = 0.f, s2 = 0.f;
    for (int r = blockIdx.x; r < n; r += gridDim.x) {
        size_t o = (size_t)r * FF + c;
        s0 += fmaxf(g_acc0[o], 0.f);
        s1 += fmaxf(g_acc1[o], 0.f);
        s2 += g_mlp[o];
    }
    atomicAdd(&g_colsum[c], s0);
    atomicAdd(&g_colsum[FF + c], s1);
    atomicAdd(&g_colsum[2 * FF + c], s2);
}

// ---------------- tiny: k_j = mean_j @ W_kj ; v_j = att_vec_j @ k_j ----------------
__global__ __launch_bounds__(256) void attn_small_kernel(
    const float* __restrict__ Wk0, const float* __restrict__ Wk1, const float* __restrict__ Wk2,
    const float* __restrict__ avA, const float* __restrict__ avA2, const float* __restrict__ avM,
    int n)
{
    __shared__ float m[3][FF];
    __shared__ float kk[3][64];
    int tid = threadIdx.x;
    float invn = 1.0f / (float)n;
    m[0][tid] = g_colsum[tid] * invn;
    m[1][tid] = g_colsum[FF + tid] * invn;
    m[2][tid] = g_colsum[2 * FF + tid] * invn;
    __syncthreads();
    int j = tid >> 6;
    int h = tid & 63;
    if (j < 3) {
        const float* Wk = (j == 0) ? Wk0 : ((j == 1) ? Wk1 : Wk2);
        float s = 0.f;
#pragma unroll 8
        for (int c = 0; c < FF; c++) s += m[j][c] * Wk[c * 64 + h];
        kk[j][h] = s;
    }
    __syncthreads();
#pragma unroll
    for (int jj = 0; jj < 3; jj++) {
        const float* av = (jj == 0) ? avA : ((jj == 1) ? avA2 : avM);
        float s = 0.f;
#pragma unroll 8
        for (int hh = 0; hh < 64; hh++) s += av[tid * 64 + hh] * kk[jj][hh];
        g_v[jj * FF + tid] = s;
    }
}

// ---------------- final: gates + weighted combine ----------------
__global__ __launch_bounds__(256) void final_kernel(
    const float* __restrict__ attvec,  // [3,3]
    float* __restrict__ out, int n)
{
    __shared__ float sv[3 * FF];
    __shared__ float sav[9];
    int tid = threadIdx.x;
    for (int i = tid; i < 3 * FF; i += 256) sv[i] = g_v[i];
    if (tid < 9) sav[tid] = attvec[tid];
    __syncthreads();

    int warp = tid >> 5;
    int lane = tid & 31;
    int node = blockIdx.x * 8 + warp;
    if (node >= n) return;

    size_t base = (size_t)node * FF;
    const float4* pa = reinterpret_cast<const float4*>(g_acc0 + base);
    const float4* pb = reinterpret_cast<const float4*>(g_acc1 + base);
    const float4* pm = reinterpret_cast<const float4*>(g_mlp + base);

    float4 a0 = pa[lane], a1 = pa[lane + 32];
    float4 b0 = pb[lane], b1 = pb[lane + 32];
    float4 m0 = pm[lane], m1 = pm[lane + 32];
    // relu on spmm outputs
    a0.x = fmaxf(a0.x, 0.f); a0.y = fmaxf(a0.y, 0.f); a0.z = fmaxf(a0.z, 0.f); a0.w = fmaxf(a0.w, 0.f);
    a1.x = fmaxf(a1.x, 0.f); a1.y = fmaxf(a1.y, 0.f); a1.z = fmaxf(a1.z, 0.f); a1.w = fmaxf(a1.w, 0.f);
    b0.x = fmaxf(b0.x, 0.f); b0.y = fmaxf(b0.y, 0.f); b0.z = fmaxf(b0.z, 0.f); b0.w = fmaxf(b0.w, 0.f);
    b1.x = fmaxf(b1.x, 0.f); b1.y = fmaxf(b1.y, 0.f); b1.z = fmaxf(b1.z, 0.f); b1.w = fmaxf(b1.w, 0.f);

    const float4* v0p = reinterpret_cast<const float4*>(sv);
    const float4* v1p = reinterpret_cast<const float4*>(sv + FF);
    const float4* v2p = reinterpret_cast<const float4*>(sv + 2 * FF);
    float4 v00 = v0p[lane], v01 = v0p[lane + 32];
    float4 v10 = v1p[lane], v11 = v1p[lane + 32];
    float4 v20 = v2p[lane], v21 = v2p[lane + 32];

    float d0 = a0.x * v00.x + a0.y * v00.y + a0.z * v00.z + a0.w * v00.w
             + a1.x * v01.x + a1.y * v01.y + a1.z * v01.z + a1.w * v01.w;
    float d1 = b0.x * v10.x + b0.y * v10.y + b0.z * v10.z + b0.w * v10.w
             + b1.x * v11.x + b1.y * v11.y + b1.z * v11.z + b1.w * v11.w;
    float d2 = m0.x * v20.x + m0.y * v20.y + m0.z * v20.z + m0.w * v20.w
             + m1.x * v21.x + m1.y * v21.y + m1.z * v21.z + m1.w * v21.w;

#pragma unroll
    for (int o = 16; o > 0; o >>= 1) {
        d0 += __shfl_xor_sync(0xffffffffu, d0, o);
        d1 += __shfl_xor_sync(0xffffffffu, d1, o);
        d2 += __shfl_xor_sync(0xffffffffu, d2, o);
    }

    float s0 = 1.f / (1.f + __expf(-d0));
    float s1 = 1.f / (1.f + __expf(-d1));
    float s2 = 1.f / (1.f + __expf(-d2));
    float zz[3];
#pragma unroll
    for (int i = 0; i < 3; i++)
        zz[i] = (s0 * sav[0 * 3 + i] + s1 * sav[1 * 3 + i] + s2 * sav[2 * 3 + i]) * (1.0f / 3.0f);
    float mx = fmaxf(zz[0], fmaxf(zz[1], zz[2]));
    float e0 = __expf(zz[0] - mx), e1 = __expf(zz[1] - mx), e2 = __expf(zz[2] - mx);
    float inv = 1.f / (e0 + e1 + e2);
    // 3 * att
    float g0 = 3.f * e0 * inv, g1 = 3.f * e1 * inv, g2 = 3.f * e2 * inv;

    float4 o0, o1;
    o0.x = g0 * a0.x + g1 * b0.x + g2 * m0.x;
    o0.y = g0 * a0.y + g1 * b0.y + g2 * m0.y;
    o0.z = g0 * a0.z + g1 * b0.z + g2 * m0.z;
    o0.w = g0 * a0.w + g1 * b0.w + g2 * m0.w;
    o1.x = g0 * a1.x + g1 * b1.x + g2 * m1.x;
    o1.y = g0 * a1.y + g1 * b1.y + g2 * m1.y;
    o1.z = g0 * a1.z + g1 * b1.z + g2 * m1.z;
    o1.w = g0 * a1.w + g1 * b1.w + g2 * m1.w;

    float4* po = reinterpret_cast<float4*>(out + base);
    po[lane] = o0;
    po[lane + 32] = o1;
}

// ---------------- launch ----------------
extern "C" void kernel_launch(void* const* d_in, const int* in_sizes, int n_in,
                              void* d_out, int out_size)
{
    const float* inputx = (const float*)d_in[0];
    const int* row_A = (const int*)d_in[1];
    const int* col_A = (const int*)d_in[2];
    const float* val_A = (const float*)d_in[3];
    const int* row_A2 = (const int*)d_in[4];
    const int* col_A2 = (const int*)d_in[5];
    const float* val_A2 = (const float*)d_in[6];
    const float* weight_A = (const float*)d_in[7];
    const float* weight_A2 = (const float*)d_in[8];
    const float* weight_mlp = (const float*)d_in[9];
    const float* W_k0 = (const float*)d_in[10];
    const float* W_k1 = (const float*)d_in[11];
    const float* W_k2 = (const float*)d_in[12];
    const float* att_vec_A = (const float*)d_in[13];
    const float* att_vec_A2 = (const float*)d_in[14];
    const float* att_vec_mlp = (const float*)d_in[15];
    const float* att_vec = (const float*)d_in[16];
    float* out = (float*)d_out;

    const int n = in_sizes[0] / FF;
    const int E = in_sizes[1];

    // 1) zero accumulators + colsum
    zero_kernel<<<148 * 8, 256>>>(n);

    // 2) three dense GEMMs
    {
        dim3 grid(FF / 64, (n + 127) / 128, 3);
        gemm_kernel<<<grid, 256>>>(inputx, weight_A, weight_A2, weight_mlp, n);
    }

    // 3) two SpMMs fused in one launch (one warp per edge; y selects matrix)
    {
        int warps_per_block = 8;
        dim3 grid((E + warps_per_block - 1) / warps_per_block, 2);
        spmm_kernel<<<grid, 256>>>(row_A, col_A, val_A, row_A2, col_A2, val_A2, E);
    }

    // 4) column means
    colsum_kernel<<<592, 256>>>(n);

    // 5) gate vectors
    attn_small_kernel<<<1, 256>>>(W_k0, W_k1, W_k2, att_vec_A, att_vec_A2, att_vec_mlp, n);

    // 6) fused gating + combine
    final_kernel<<<(n + 7) / 8, 256>>>(att_vec, out, n);
}